// round 12
// baseline (speedup 1.0000x reference)
#include <cuda_runtime.h>
#include <cstdint>

#define BS      512
#define DIM     128
#define POS_K   32
#define NUM_NEG 1024
#define INV_TEMP (1.0f / 0.07f)

#define NBLK    256                   // exactly one resident wave (2/SM)
#define D_ST    4                     // per-warp ring depth
#define NST     128                   // total stages (2048 refs / 16 per stage)
#define NREF    2048                  // 2 reps * 1024 negatives

// Output layout (flattened tuple, float32):
#define O0 0          // inst_v2a_pos [512,1]
#define O1 512        // inst_v2a_neg [512,1024]
#define O2 524800     // inst_a2v_pos [512,1]
#define O3 525312     // inst_a2v_neg [512,1024]
#define O4 1049600    // pos_v2v_pos  [512,32]
#define O5 1065984    // pos_v2v_neg  [512,1024]
#define O6 1590272    // pos_a2a_pos  [512,32]
#define O7 1606656    // pos_a2a_neg  [512,1024]

#define FULL 0xffffffffu

__device__ int g_bar[8];

__global__ void reset_bar_kernel() {
    if (threadIdx.x < 8) g_bar[threadIdx.x] = 0;
}

__device__ __forceinline__ float warp_sum(float x) {
#pragma unroll
    for (int o = 16; o; o >>= 1) x += __shfl_xor_sync(FULL, x, o);
    return x;
}

__device__ __forceinline__ float dot4(float4 x, float4 y) {
    return x.x * y.x + x.y * y.y + x.z * y.z + x.w * y.w;
}

__device__ __forceinline__ void grp8_sum2(float& a, float& b) {
#pragma unroll
    for (int o = 4; o; o >>= 1) {
        a += __shfl_xor_sync(FULL, a, o);
        b += __shfl_xor_sync(FULL, b, o);
    }
}

__device__ __forceinline__ void cp_async16(uint32_t dst_smem, const void* src) {
    asm volatile("cp.async.cg.shared.global [%0], [%1], 16;\n"
                 :: "r"(dst_smem), "l"(src) : "memory");
}
__device__ __forceinline__ void cp_commit() {
    asm volatile("cp.async.commit_group;\n" ::: "memory");
}
template <int N>
__device__ __forceinline__ void cp_wait() {
    asm volatile("cp.async.wait_group %0;\n" :: "n"(N) : "memory");
}

// grid-wide throttle barrier: safe, all NBLK blocks co-resident (one wave).
// Does NOT drain the cp.async pipeline — per-warp groups stay in flight.
__device__ __forceinline__ void grid_bar(int k) {
    __syncthreads();
    if (threadIdx.x == 0) {
        atomicAdd(&g_bar[k], 1);
        while (atomicAdd(&g_bar[k], 0) < NBLK) __nanosleep(64);
    }
    __syncthreads();
}

__global__ __launch_bounds__(256, 2)
void avid_cma_kernel(const float* __restrict__ video,
                     const float* __restrict__ audio,
                     const float4* __restrict__ m1,
                     const float4* __restrict__ m2,
                     const int* __restrict__ y,
                     const int* __restrict__ pos_idx,
                     const int* __restrict__ neg_idx,
                     float* __restrict__ out)
{
    extern __shared__ char ring[];              // 8 warps * D_ST * 2048 = 64 KB
    __shared__ uint32_t sorted[NREF];           // 8 KB merged sorted keys
    __shared__ int      counts[64];
    __shared__ int      ocur[64];
    __shared__ float4   sv[2][32];
    __shared__ float4   sa[2][32];
    __shared__ float    sout[2][4][NUM_NEG];    // 32 KB output staging

    const int tid  = threadIdx.x;
    const int lane = tid & 31;
    const int w    = tid >> 5;                  // 8 warps
    const int c    = lane & 7;
    const int r    = lane >> 3;
    char* const wring = ring + (size_t)w * (D_ST * 2048);

    // ---- normalize all 4 fresh vectors (warps 0..3) ----
    if (w < 4) {
        const int rr = w >> 1;
        const int bb = blockIdx.x + rr * NBLK;
        const float* srcv = (w & 1) ? audio : video;
        float4 x = reinterpret_cast<const float4*>(srcv)[bb * 32 + lane];
        float ss = warp_sum(dot4(x, x));
        float inv = 1.0f / fmaxf(sqrtf(ss), 1e-12f);
        float4 nv = make_float4(x.x * inv, x.y * inv, x.z * inv, x.w * inv);
        if (w & 1) sa[rr][lane] = nv; else sv[rr][lane] = nv;
    }
    if (tid < 64) counts[tid] = 0;
    __syncthreads();

    // ---- merged counting sort: 2048 keys, 64 buckets (row >> 13) ----
    // pass 1: count (read indices from gmem, coalesced)
#pragma unroll
    for (int i = tid; i < NREF; i += 256) {
        const int rep = i >> 10, j = i & 1023;
        const int b = blockIdx.x + rep * NBLK;
        const uint32_t row = (uint32_t)__ldg(neg_idx + (size_t)b * NUM_NEG + j);
        atomicAdd(&counts[row >> 13], 1);
    }
    __syncthreads();
    if (tid == 0) {
        int acc = 0;
#pragma unroll
        for (int k = 0; k < 64; ++k) { ocur[k] = acc; acc += counts[k]; }
    }
    __syncthreads();
    // pass 2: scatter (re-read indices; L2-hot)
#pragma unroll
    for (int i = tid; i < NREF; i += 256) {
        const int rep = i >> 10, j = i & 1023;
        const int b = blockIdx.x + rep * NBLK;
        const uint32_t row = (uint32_t)__ldg(neg_idx + (size_t)b * NUM_NEG + j);
        const int p = atomicAdd(&ocur[row >> 13], 1);
        sorted[p] = (row << 11) | ((uint32_t)rep << 10) | (uint32_t)j;
    }
    __syncthreads();                            // sorted + sv/sa ready

#define ISSUE(gexp)                                                           \
    do {                                                                      \
        const int g_loc = (gexp);                                             \
        _Pragma("unroll")                                                     \
        for (int i = 0; i < 4; ++i) {                                         \
            const int p = g_loc * 16 + w * 2 + (i >> 1);                      \
            const int ni = (int)(sorted[p] >> 11);                            \
            const float4* src = ((i & 1) ? m2 : m1) + (size_t)ni * 32 + lane; \
            uint32_t dst = (uint32_t)__cvta_generic_to_shared(                \
                wring + ((g_loc % D_ST) * 2048) + i * 512 + lane * 16);       \
            cp_async16(dst, src);                                             \
        }                                                                     \
    } while (0)

    // ---- prologue: issue stages 0..D_ST-2 ----
#pragma unroll
    for (int g = 0; g < D_ST - 1; ++g) { ISSUE(g); cp_commit(); }

    // ---- pos + self dots for both reps (direct LDG, overlaps fill) ----
    for (int rep = 0; rep < 2; ++rep) {
        const int bp = blockIdx.x + rep * NBLK;
        const float4 v0 = sv[rep][c], v1 = sv[rep][c + 8], v2 = sv[rep][c + 16], v3 = sv[rep][c + 24];
        const float4 a0 = sa[rep][c], a1 = sa[rep][c + 8], a2 = sa[rep][c + 16], a3 = sa[rep][c + 24];
        const int j  = w * 4 + r;
        const int pi = __ldg(pos_idx + (size_t)bp * POS_K + j);
        const float4* p1 = m1 + (size_t)pi * 32 + c;
        const float4* p2 = m2 + (size_t)pi * 32 + c;
        float dvv = dot4(p1[0], v0) + dot4(p1[8], v1) + dot4(p1[16], v2) + dot4(p1[24], v3);
        float daa = dot4(p2[0], a0) + dot4(p2[8], a1) + dot4(p2[16], a2) + dot4(p2[24], a3);
        grp8_sum2(dvv, daa);
        if (c == 0) {
            out[O4 + (size_t)bp * POS_K + j] = dvv * INV_TEMP;
            out[O6 + (size_t)bp * POS_K + j] = daa * INV_TEMP;
        }
        if (w == 0 && r < 2) {
            const int yi = __ldg(y + bp);
            const float4* p = (r == 0 ? m1 : m2) + (size_t)yi * 32 + c;
            float d;
            if (r == 0) d = dot4(p[0], a0) + dot4(p[8], a1) + dot4(p[16], a2) + dot4(p[24], a3);
            else        d = dot4(p[0], v0) + dot4(p[8], v1) + dot4(p[16], v2) + dot4(p[24], v3);
#pragma unroll
            for (int o = 4; o; o >>= 1) d += __shfl_xor_sync(0x0000ffffu, d, o);
            if (c == 0) {
                if (r == 0) out[O2 + bp] = d * INV_TEMP;
                else        out[O0 + bp] = d * INV_TEMP;
            }
        }
    }

    // ---- single continuous sweep: 128 stages, throttle at 32/64/96 ----
    for (int s = 0; s < NST; ++s) {
        if ((s & 31) == 0 && s != 0) grid_bar((s >> 5) - 1);  // no drain

        const int sn = s + D_ST - 1;
        if (sn < NST) {
            cp_wait<D_ST - 2>();                // stage s complete
            __syncwarp();
            ISSUE(sn);
            cp_commit();
        } else {
            cp_wait<0>();                       // strict tail drain
            __syncwarp();
        }

        // this group's ref: sorted[s*16 + w*2 + (r>>1)], bank r&1
        const uint32_t key = sorted[s * 16 + w * 2 + (r >> 1)];
        const int rep = (int)((key >> 10) & 1u);
        const float4 v0 = sv[rep][c], v1 = sv[rep][c + 8], v2 = sv[rep][c + 16], v3 = sv[rep][c + 24];
        const float4 a0 = sa[rep][c], a1 = sa[rep][c + 8], a2 = sa[rep][c + 16], a3 = sa[rep][c + 24];

        const float4* buf = reinterpret_cast<const float4*>(
            wring + (s % D_ST) * 2048) + (size_t)r * 32;
        const float4 x0 = buf[c], x1 = buf[c + 8], x2 = buf[c + 16], x3 = buf[c + 24];
        float dv = dot4(x0, v0) + dot4(x1, v1) + dot4(x2, v2) + dot4(x3, v3);
        float da = dot4(x0, a0) + dot4(x1, a1) + dot4(x2, a2) + dot4(x3, a3);
        grp8_sum2(dv, da);

        if (c == 0) {
            const int j = (int)(key & 1023u);
            if ((r & 1) == 0) {                 // m1 row: ·a -> O3, ·v -> O5
                sout[rep][1][j] = da * INV_TEMP;
                sout[rep][2][j] = dv * INV_TEMP;
            } else {                            // m2 row: ·v -> O1, ·a -> O7
                sout[rep][0][j] = dv * INV_TEMP;
                sout[rep][3][j] = da * INV_TEMP;
            }
        }
    }
#undef ISSUE

    // ---- coalesced output flush ----
    __syncthreads();
    for (int rep = 0; rep < 2; ++rep) {
        const int b = blockIdx.x + rep * NBLK;
        for (int i = tid; i < NUM_NEG; i += 256) {
            const size_t o = (size_t)b * NUM_NEG + i;
            out[O1 + o] = sout[rep][0][i];
            out[O3 + o] = sout[rep][1][i];
            out[O5 + o] = sout[rep][2][i];
            out[O7 + o] = sout[rep][3][i];
        }
    }
}

extern "C" void kernel_launch(void* const* d_in, const int* in_sizes, int n_in,
                              void* d_out, int out_size)
{
    const float* video = (const float*)d_in[0];
    const float* audio = (const float*)d_in[1];
    const float4* m1   = (const float4*)d_in[2];
    const float4* m2   = (const float4*)d_in[3];
    const int* y       = (const int*)d_in[4];
    const int* pos_idx = (const int*)d_in[5];
    const int* neg_idx = (const int*)d_in[6];
    float* out         = (float*)d_out;

    const int dyn_smem = 8 * D_ST * 2048;   // 64 KB
    cudaFuncSetAttribute(avid_cma_kernel,
                         cudaFuncAttributeMaxDynamicSharedMemorySize, dyn_smem);

    reset_bar_kernel<<<1, 32>>>();
    avid_cma_kernel<<<NBLK, 256, dyn_smem>>>(video, audio, m1, m2, y,
                                             pos_idx, neg_idx, out);
}

// round 13
// speedup vs baseline: 1.0818x; 1.0818x over previous
#include <cuda_runtime.h>
#include <cstdint>

#define BS      512
#define DIM     128
#define POS_K   32
#define NUM_NEG 1024
#define INV_TEMP (1.0f / 0.07f)

#define NBLK    256                   // one resident wave (2/SM)
#define D_ST    4                     // per-warp ring depth
#define NST     128                   // total stages (2048 refs / 16 per stage)
#define NREF    2048                  // 2 reps * 1024 negatives

// Output layout (flattened tuple, float32):
#define O0 0          // inst_v2a_pos [512,1]
#define O1 512        // inst_v2a_neg [512,1024]
#define O2 524800     // inst_a2v_pos [512,1]
#define O3 525312     // inst_a2v_neg [512,1024]
#define O4 1049600    // pos_v2v_pos  [512,32]
#define O5 1065984    // pos_v2v_neg  [512,1024]
#define O6 1590272    // pos_a2a_pos  [512,32]
#define O7 1606656    // pos_a2a_neg  [512,1024]

#define FULL 0xffffffffu

__device__ __forceinline__ float warp_sum(float x) {
#pragma unroll
    for (int o = 16; o; o >>= 1) x += __shfl_xor_sync(FULL, x, o);
    return x;
}

__device__ __forceinline__ float dot4(float4 x, float4 y) {
    return x.x * y.x + x.y * y.y + x.z * y.z + x.w * y.w;
}

__device__ __forceinline__ void grp8_sum2(float& a, float& b) {
#pragma unroll
    for (int o = 4; o; o >>= 1) {
        a += __shfl_xor_sync(FULL, a, o);
        b += __shfl_xor_sync(FULL, b, o);
    }
}

__device__ __forceinline__ void cp_async16(uint32_t dst_smem, const void* src) {
    asm volatile("cp.async.cg.shared.global [%0], [%1], 16;\n"
                 :: "r"(dst_smem), "l"(src) : "memory");
}
__device__ __forceinline__ void cp_commit() {
    asm volatile("cp.async.commit_group;\n" ::: "memory");
}
template <int N>
__device__ __forceinline__ void cp_wait() {
    asm volatile("cp.async.wait_group %0;\n" :: "n"(N) : "memory");
}

__global__ __launch_bounds__(256, 2)
void avid_cma_kernel(const float* __restrict__ video,
                     const float* __restrict__ audio,
                     const float4* __restrict__ m1,
                     const float4* __restrict__ m2,
                     const int* __restrict__ y,
                     const int* __restrict__ pos_idx,
                     const int* __restrict__ neg_idx,
                     float* __restrict__ out)
{
    extern __shared__ char ring[];              // 8 warps * D_ST * 2048 = 64 KB
    __shared__ uint32_t sorted[NREF];           // 8 KB merged sorted keys
    __shared__ int      counts[64];
    __shared__ int      ocur[64];
    __shared__ float4   sv[2][32];
    __shared__ float4   sa[2][32];
    __shared__ float    sout[2][4][NUM_NEG];    // 32 KB output staging

    const int tid  = threadIdx.x;
    const int lane = tid & 31;
    const int w    = tid >> 5;                  // 8 warps
    const int c    = lane & 7;
    const int r    = lane >> 3;
    char* const wring = ring + (size_t)w * (D_ST * 2048);

    // ---- normalize all 4 fresh vectors (warps 0..3) ----
    if (w < 4) {
        const int rr = w >> 1;
        const int bb = blockIdx.x + rr * NBLK;
        const float* srcv = (w & 1) ? audio : video;
        float4 x = reinterpret_cast<const float4*>(srcv)[bb * 32 + lane];
        float ss = warp_sum(dot4(x, x));
        float inv = 1.0f / fmaxf(sqrtf(ss), 1e-12f);
        float4 nv = make_float4(x.x * inv, x.y * inv, x.z * inv, x.w * inv);
        if (w & 1) sa[rr][lane] = nv; else sv[rr][lane] = nv;
    }
    if (tid < 64) counts[tid] = 0;
    __syncthreads();

    // ---- merged counting sort: 2048 keys, 64 buckets (row >> 13) ----
#pragma unroll
    for (int i = tid; i < NREF; i += 256) {
        const int rep = i >> 10, j = i & 1023;
        const int b = blockIdx.x + rep * NBLK;
        const uint32_t row = (uint32_t)__ldg(neg_idx + (size_t)b * NUM_NEG + j);
        atomicAdd(&counts[row >> 13], 1);
    }
    __syncthreads();
    if (tid == 0) {
        int acc = 0;
#pragma unroll
        for (int k = 0; k < 64; ++k) { ocur[k] = acc; acc += counts[k]; }
    }
    __syncthreads();
#pragma unroll
    for (int i = tid; i < NREF; i += 256) {
        const int rep = i >> 10, j = i & 1023;
        const int b = blockIdx.x + rep * NBLK;
        const uint32_t row = (uint32_t)__ldg(neg_idx + (size_t)b * NUM_NEG + j);
        const int p = atomicAdd(&ocur[row >> 13], 1);
        sorted[p] = (row << 11) | ((uint32_t)rep << 10) | (uint32_t)j;
    }
    __syncthreads();                            // sorted + sv/sa ready

#define ISSUE(gexp)                                                           \
    do {                                                                      \
        const int g_loc = (gexp);                                             \
        _Pragma("unroll")                                                     \
        for (int i = 0; i < 4; ++i) {                                         \
            const int p = g_loc * 16 + w * 2 + (i >> 1);                      \
            const int ni = (int)(sorted[p] >> 11);                            \
            const float4* src = ((i & 1) ? m2 : m1) + (size_t)ni * 32 + lane; \
            uint32_t dst = (uint32_t)__cvta_generic_to_shared(                \
                wring + ((g_loc % D_ST) * 2048) + i * 512 + lane * 16);       \
            cp_async16(dst, src);                                             \
        }                                                                     \
    } while (0)

    // ---- prologue: issue stages 0..D_ST-2 ----
#pragma unroll
    for (int g = 0; g < D_ST - 1; ++g) { ISSUE(g); cp_commit(); }

    // ---- pos + self dots for both reps (direct LDG, overlaps fill) ----
    for (int rep = 0; rep < 2; ++rep) {
        const int bp = blockIdx.x + rep * NBLK;
        const float4 v0 = sv[rep][c], v1 = sv[rep][c + 8], v2 = sv[rep][c + 16], v3 = sv[rep][c + 24];
        const float4 a0 = sa[rep][c], a1 = sa[rep][c + 8], a2 = sa[rep][c + 16], a3 = sa[rep][c + 24];
        const int j  = w * 4 + r;
        const int pi = __ldg(pos_idx + (size_t)bp * POS_K + j);
        const float4* p1 = m1 + (size_t)pi * 32 + c;
        const float4* p2 = m2 + (size_t)pi * 32 + c;
        float dvv = dot4(p1[0], v0) + dot4(p1[8], v1) + dot4(p1[16], v2) + dot4(p1[24], v3);
        float daa = dot4(p2[0], a0) + dot4(p2[8], a1) + dot4(p2[16], a2) + dot4(p2[24], a3);
        grp8_sum2(dvv, daa);
        if (c == 0) {
            out[O4 + (size_t)bp * POS_K + j] = dvv * INV_TEMP;
            out[O6 + (size_t)bp * POS_K + j] = daa * INV_TEMP;
        }
        if (w == 0 && r < 2) {
            const int yi = __ldg(y + bp);
            const float4* p = (r == 0 ? m1 : m2) + (size_t)yi * 32 + c;
            float d;
            if (r == 0) d = dot4(p[0], a0) + dot4(p[8], a1) + dot4(p[16], a2) + dot4(p[24], a3);
            else        d = dot4(p[0], v0) + dot4(p[8], v1) + dot4(p[16], v2) + dot4(p[24], v3);
#pragma unroll
            for (int o = 4; o; o >>= 1) d += __shfl_xor_sync(0x0000ffffu, d, o);
            if (c == 0) {
                if (r == 0) out[O2 + bp] = d * INV_TEMP;
                else        out[O0 + bp] = d * INV_TEMP;
            }
        }
    }

    // ---- single continuous sorted sweep: 128 stages, NO grid barriers ----
    for (int s = 0; s < NST; ++s) {
        const int sn = s + D_ST - 1;
        if (sn < NST) {
            cp_wait<D_ST - 2>();                // stage s complete
            __syncwarp();
            ISSUE(sn);
            cp_commit();
        } else {
            cp_wait<0>();                       // strict tail drain
            __syncwarp();
        }

        // this group's ref: sorted[s*16 + w*2 + (r>>1)], bank r&1
        const uint32_t key = sorted[s * 16 + w * 2 + (r >> 1)];
        const int rep = (int)((key >> 10) & 1u);
        const float4 v0 = sv[rep][c], v1 = sv[rep][c + 8], v2 = sv[rep][c + 16], v3 = sv[rep][c + 24];
        const float4 a0 = sa[rep][c], a1 = sa[rep][c + 8], a2 = sa[rep][c + 16], a3 = sa[rep][c + 24];

        const float4* buf = reinterpret_cast<const float4*>(
            wring + (s % D_ST) * 2048) + (size_t)r * 32;
        const float4 x0 = buf[c], x1 = buf[c + 8], x2 = buf[c + 16], x3 = buf[c + 24];
        float dv = dot4(x0, v0) + dot4(x1, v1) + dot4(x2, v2) + dot4(x3, v3);
        float da = dot4(x0, a0) + dot4(x1, a1) + dot4(x2, a2) + dot4(x3, a3);
        grp8_sum2(dv, da);

        if (c == 0) {
            const int j = (int)(key & 1023u);
            if ((r & 1) == 0) {                 // m1 row: ·a -> O3, ·v -> O5
                sout[rep][1][j] = da * INV_TEMP;
                sout[rep][2][j] = dv * INV_TEMP;
            } else {                            // m2 row: ·v -> O1, ·a -> O7
                sout[rep][0][j] = dv * INV_TEMP;
                sout[rep][3][j] = da * INV_TEMP;
            }
        }
    }
#undef ISSUE

    // ---- coalesced output flush ----
    __syncthreads();
    for (int rep = 0; rep < 2; ++rep) {
        const int b = blockIdx.x + rep * NBLK;
        for (int i = tid; i < NUM_NEG; i += 256) {
            const size_t o = (size_t)b * NUM_NEG + i;
            out[O1 + o] = sout[rep][0][i];
            out[O3 + o] = sout[rep][1][i];
            out[O5 + o] = sout[rep][2][i];
            out[O7 + o] = sout[rep][3][i];
        }
    }
}

extern "C" void kernel_launch(void* const* d_in, const int* in_sizes, int n_in,
                              void* d_out, int out_size)
{
    const float* video = (const float*)d_in[0];
    const float* audio = (const float*)d_in[1];
    const float4* m1   = (const float4*)d_in[2];
    const float4* m2   = (const float4*)d_in[3];
    const int* y       = (const int*)d_in[4];
    const int* pos_idx = (const int*)d_in[5];
    const int* neg_idx = (const int*)d_in[6];
    float* out         = (float*)d_out;

    const int dyn_smem = 8 * D_ST * 2048;   // 64 KB
    cudaFuncSetAttribute(avid_cma_kernel,
                         cudaFuncAttributeMaxDynamicSharedMemorySize, dyn_smem);

    avid_cma_kernel<<<NBLK, 256, dyn_smem>>>(video, audio, m1, m2, y,
                                             pos_idx, neg_idx, out);
}

// round 14
// speedup vs baseline: 1.5080x; 1.3940x over previous
#include <cuda_runtime.h>
#include <cstdint>

#define BS      512
#define DIM     128
#define POS_K   32
#define NUM_NEG 1024
#define INV_TEMP (1.0f / 0.07f)

#define NBLK    256                   // one resident wave (2/SM)
#define D_ST    4                     // per-warp ring depth
#define NST     128                   // stages per warp (1024 refs/rep / 8 per stage)

// Output layout (flattened tuple, float32):
#define O0 0          // inst_v2a_pos [512,1]
#define O1 512        // inst_v2a_neg [512,1024]
#define O2 524800     // inst_a2v_pos [512,1]
#define O3 525312     // inst_a2v_neg [512,1024]
#define O4 1049600    // pos_v2v_pos  [512,32]
#define O5 1065984    // pos_v2v_neg  [512,1024]
#define O6 1590272    // pos_a2a_pos  [512,32]
#define O7 1606656    // pos_a2a_neg  [512,1024]

#define FULL 0xffffffffu

__device__ __forceinline__ float warp_sum(float x) {
#pragma unroll
    for (int o = 16; o; o >>= 1) x += __shfl_xor_sync(FULL, x, o);
    return x;
}

__device__ __forceinline__ float dot4(float4 x, float4 y) {
    return x.x * y.x + x.y * y.y + x.z * y.z + x.w * y.w;
}

__device__ __forceinline__ void grp8_sum2(float& a, float& b) {
#pragma unroll
    for (int o = 4; o; o >>= 1) {
        a += __shfl_xor_sync(FULL, a, o);
        b += __shfl_xor_sync(FULL, b, o);
    }
}

__device__ __forceinline__ void cp_async16(uint32_t dst_smem, const void* src) {
    asm volatile("cp.async.cg.shared.global [%0], [%1], 16;\n"
                 :: "r"(dst_smem), "l"(src) : "memory");
}
__device__ __forceinline__ void cp_commit() {
    asm volatile("cp.async.commit_group;\n" ::: "memory");
}
template <int N>
__device__ __forceinline__ void cp_wait() {
    asm volatile("cp.async.wait_group %0;\n" :: "n"(N) : "memory");
}

__global__ __launch_bounds__(256, 2)
void avid_cma_kernel(const float* __restrict__ video,
                     const float* __restrict__ audio,
                     const float4* __restrict__ m1,
                     const float4* __restrict__ m2,
                     const int* __restrict__ y,
                     const int* __restrict__ pos_idx,
                     const int* __restrict__ neg_idx,
                     float* __restrict__ out)
{
    extern __shared__ char ring[];              // 8 warps * D_ST * 2048 = 64 KB
    __shared__ uint32_t sorted[2][NUM_NEG];     // 8 KB per-rep sorted keys
    __shared__ int      counts[64];
    __shared__ int      ocur[64];
    __shared__ float4   sv[2][32];
    __shared__ float4   sa[2][32];
    __shared__ float    sout[2][4][NUM_NEG];    // 32 KB output staging

    const int tid  = threadIdx.x;
    const int lane = tid & 31;
    const int w    = tid >> 5;                  // 8 warps
    const int c    = lane & 7;
    const int r    = lane >> 3;
    const int wrep = w >> 2;                    // warp's static rep (0 or 1)
    const int wq   = w & 3;                     // warp's lane within rep group
    char* const wring = ring + (size_t)w * (D_ST * 2048);

    // ---- normalize all 4 fresh vectors (warps 0..3) ----
    if (w < 4) {
        const int rr = w >> 1;
        const int bb = blockIdx.x + rr * NBLK;
        const float* srcv = (w & 1) ? audio : video;
        float4 x = reinterpret_cast<const float4*>(srcv)[bb * 32 + lane];
        float ss = warp_sum(dot4(x, x));
        float inv = 1.0f / fmaxf(sqrtf(ss), 1e-12f);
        float4 nv = make_float4(x.x * inv, x.y * inv, x.z * inv, x.w * inv);
        if (w & 1) sa[rr][lane] = nv; else sv[rr][lane] = nv;
    }

    // ---- per-rep counting sort: 1024 keys, 64 buckets (row >> 13) ----
    for (int rep = 0; rep < 2; ++rep) {
        const int b = blockIdx.x + rep * NBLK;
        if (tid < 64) counts[tid] = 0;
        __syncthreads();
#pragma unroll
        for (int i = tid; i < NUM_NEG; i += 256) {
            const uint32_t row = (uint32_t)__ldg(neg_idx + (size_t)b * NUM_NEG + i);
            atomicAdd(&counts[row >> 13], 1);
        }
        __syncthreads();
        if (tid == 0) {
            int acc = 0;
#pragma unroll
            for (int k = 0; k < 64; ++k) { ocur[k] = acc; acc += counts[k]; }
        }
        __syncthreads();
#pragma unroll
        for (int i = tid; i < NUM_NEG; i += 256) {
            const uint32_t row = (uint32_t)__ldg(neg_idx + (size_t)b * NUM_NEG + i);
            const int p = atomicAdd(&ocur[row >> 13], 1);
            sorted[rep][p] = (row << 10) | (uint32_t)i;
        }
        __syncthreads();
    }

    // this warp's rep: v/a slices in REGISTERS (the R13 fix)
    const float4 v0 = sv[wrep][c], v1 = sv[wrep][c + 8], v2 = sv[wrep][c + 16], v3 = sv[wrep][c + 24];
    const float4 a0 = sa[wrep][c], a1 = sa[wrep][c + 8], a2 = sa[wrep][c + 16], a3 = sa[wrep][c + 24];
    const uint32_t* skeys = sorted[wrep];

#define ISSUE(gexp)                                                           \
    do {                                                                      \
        const int g_loc = (gexp);                                             \
        _Pragma("unroll")                                                     \
        for (int i = 0; i < 4; ++i) {                                         \
            const int p = g_loc * 8 + wq * 2 + (i >> 1);                      \
            const int ni = (int)(skeys[p] >> 10);                             \
            const float4* src = ((i & 1) ? m2 : m1) + (size_t)ni * 32 + lane; \
            uint32_t dst = (uint32_t)__cvta_generic_to_shared(                \
                wring + ((g_loc % D_ST) * 2048) + i * 512 + lane * 16);       \
            cp_async16(dst, src);                                             \
        }                                                                     \
    } while (0)

    // ---- prologue: issue stages 0..D_ST-2 ----
#pragma unroll
    for (int g = 0; g < D_ST - 1; ++g) { ISSUE(g); cp_commit(); }

    // ---- pos + self dots for both reps (direct LDG, overlaps fill) ----
    {
        const int bp = blockIdx.x + wrep * NBLK;
        // each rep group (4 warps) covers its rep's 32 positives: j = wq*8 + r*2 + {0,1}
#pragma unroll
        for (int t = 0; t < 2; ++t) {
            const int j  = wq * 8 + r * 2 + t;
            const int pi = __ldg(pos_idx + (size_t)bp * POS_K + j);
            const float4* p1 = m1 + (size_t)pi * 32 + c;
            const float4* p2 = m2 + (size_t)pi * 32 + c;
            float dvv = dot4(p1[0], v0) + dot4(p1[8], v1) + dot4(p1[16], v2) + dot4(p1[24], v3);
            float daa = dot4(p2[0], a0) + dot4(p2[8], a1) + dot4(p2[16], a2) + dot4(p2[24], a3);
            grp8_sum2(dvv, daa);
            if (c == 0) {
                out[O4 + (size_t)bp * POS_K + j] = dvv * INV_TEMP;
                out[O6 + (size_t)bp * POS_K + j] = daa * INV_TEMP;
            }
        }
        if (wq == 0 && r < 2) {   // warps 0 and 4 handle self dots for their rep
            const int yi = __ldg(y + bp);
            const float4* p = (r == 0 ? m1 : m2) + (size_t)yi * 32 + c;
            float d;
            if (r == 0) d = dot4(p[0], a0) + dot4(p[8], a1) + dot4(p[16], a2) + dot4(p[24], a3);
            else        d = dot4(p[0], v0) + dot4(p[8], v1) + dot4(p[16], v2) + dot4(p[24], v3);
#pragma unroll
            for (int o = 4; o; o >>= 1) d += __shfl_xor_sync(0x0000ffffu, d, o);
            if (c == 0) {
                if (r == 0) out[O2 + bp] = d * INV_TEMP;  // inst_a2v_pos
                else        out[O0 + bp] = d * INV_TEMP;  // inst_v2a_pos
            }
        }
    }

    // ---- continuous sorted sweep: 128 stages/warp, rep static per warp ----
    for (int s = 0; s < NST; ++s) {
        const int sn = s + D_ST - 1;
        if (sn < NST) {
            cp_wait<D_ST - 2>();                // stage s complete
            __syncwarp();
            ISSUE(sn);
            cp_commit();
        } else {
            cp_wait<0>();                       // strict tail drain
            __syncwarp();
        }

        // group r handles row slot r: neg p = s*8 + wq*2 + (r>>1), bank r&1
        const float4* buf = reinterpret_cast<const float4*>(
            wring + (s % D_ST) * 2048) + (size_t)r * 32;
        const float4 x0 = buf[c], x1 = buf[c + 8], x2 = buf[c + 16], x3 = buf[c + 24];
        float dv = dot4(x0, v0) + dot4(x1, v1) + dot4(x2, v2) + dot4(x3, v3);
        float da = dot4(x0, a0) + dot4(x1, a1) + dot4(x2, a2) + dot4(x3, a3);
        grp8_sum2(dv, da);

        if (c == 0) {
            const int j = (int)(skeys[s * 8 + wq * 2 + (r >> 1)] & 1023u);
            if ((r & 1) == 0) {                 // m1 row: ·a -> O3, ·v -> O5
                sout[wrep][1][j] = da * INV_TEMP;
                sout[wrep][2][j] = dv * INV_TEMP;
            } else {                            // m2 row: ·v -> O1, ·a -> O7
                sout[wrep][0][j] = dv * INV_TEMP;
                sout[wrep][3][j] = da * INV_TEMP;
            }
        }
    }
#undef ISSUE

    // ---- coalesced output flush ----
    __syncthreads();
    for (int rep = 0; rep < 2; ++rep) {
        const int b = blockIdx.x + rep * NBLK;
        for (int i = tid; i < NUM_NEG; i += 256) {
            const size_t o = (size_t)b * NUM_NEG + i;
            out[O1 + o] = sout[rep][0][i];
            out[O3 + o] = sout[rep][1][i];
            out[O5 + o] = sout[rep][2][i];
            out[O7 + o] = sout[rep][3][i];
        }
    }
}

extern "C" void kernel_launch(void* const* d_in, const int* in_sizes, int n_in,
                              void* d_out, int out_size)
{
    const float* video = (const float*)d_in[0];
    const float* audio = (const float*)d_in[1];
    const float4* m1   = (const float4*)d_in[2];
    const float4* m2   = (const float4*)d_in[3];
    const int* y       = (const int*)d_in[4];
    const int* pos_idx = (const int*)d_in[5];
    const int* neg_idx = (const int*)d_in[6];
    float* out         = (float*)d_out;

    const int dyn_smem = 8 * D_ST * 2048;   // 64 KB
    cudaFuncSetAttribute(avid_cma_kernel,
                         cudaFuncAttributeMaxDynamicSharedMemorySize, dyn_smem);

    avid_cma_kernel<<<NBLK, 256, dyn_smem>>>(video, audio, m1, m2, y,
                                             pos_idx, neg_idx, out);
}

// round 15
// speedup vs baseline: 1.5871x; 1.0525x over previous
#include <cuda_runtime.h>
#include <cstdint>

#define BS      512
#define DIM     128
#define POS_K   32
#define NUM_NEG 1024
#define INV_TEMP (1.0f / 0.07f)

#define NBLK    256                   // one resident wave (2/SM)
#define D_ST    4                     // per-warp ring depth
#define NST     128                   // stages per warp (1024 refs/rep / 8 per stage)
#define NBKT    256                   // sort buckets (row >> 11)

// Output layout (flattened tuple, float32):
#define O0 0          // inst_v2a_pos [512,1]
#define O1 512        // inst_v2a_neg [512,1024]
#define O2 524800     // inst_a2v_pos [512,1]
#define O3 525312     // inst_a2v_neg [512,1024]
#define O4 1049600    // pos_v2v_pos  [512,32]
#define O5 1065984    // pos_v2v_neg  [512,1024]
#define O6 1590272    // pos_a2a_pos  [512,32]
#define O7 1606656    // pos_a2a_neg  [512,1024]

#define FULL 0xffffffffu

__device__ __forceinline__ float warp_sum(float x) {
#pragma unroll
    for (int o = 16; o; o >>= 1) x += __shfl_xor_sync(FULL, x, o);
    return x;
}

__device__ __forceinline__ float dot4(float4 x, float4 y) {
    return x.x * y.x + x.y * y.y + x.z * y.z + x.w * y.w;
}

__device__ __forceinline__ void grp8_sum2(float& a, float& b) {
#pragma unroll
    for (int o = 4; o; o >>= 1) {
        a += __shfl_xor_sync(FULL, a, o);
        b += __shfl_xor_sync(FULL, b, o);
    }
}

__device__ __forceinline__ void cp_async16(uint32_t dst_smem, const void* src) {
    asm volatile("cp.async.cg.shared.global [%0], [%1], 16;\n"
                 :: "r"(dst_smem), "l"(src) : "memory");
}
__device__ __forceinline__ void cp_commit() {
    asm volatile("cp.async.commit_group;\n" ::: "memory");
}
template <int N>
__device__ __forceinline__ void cp_wait() {
    asm volatile("cp.async.wait_group %0;\n" :: "n"(N) : "memory");
}

__global__ __launch_bounds__(256, 2)
void avid_cma_kernel(const float* __restrict__ video,
                     const float* __restrict__ audio,
                     const float4* __restrict__ m1,
                     const float4* __restrict__ m2,
                     const int* __restrict__ y,
                     const int* __restrict__ pos_idx,
                     const int* __restrict__ neg_idx,
                     float* __restrict__ out)
{
    extern __shared__ char ring[];              // 8 warps * D_ST * 2048 = 64 KB
    __shared__ uint32_t sorted[2][NUM_NEG];     // 8 KB per-rep sorted keys
    __shared__ int      counts[NBKT];           // 1 KB
    __shared__ int      ocur[NBKT];             // 1 KB
    __shared__ float4   sv[2][32];
    __shared__ float4   sa[2][32];
    __shared__ float    sout[2][4][NUM_NEG];    // 32 KB output staging

    const int tid  = threadIdx.x;
    const int lane = tid & 31;
    const int w    = tid >> 5;                  // 8 warps
    const int c    = lane & 7;
    const int r    = lane >> 3;
    const int wrep = w >> 2;                    // warp's static rep (0 or 1)
    const int wq   = w & 3;                     // warp's slot within rep group
    char* const wring = ring + (size_t)w * (D_ST * 2048);

    // ---- normalize all 4 fresh vectors (warps 0..3) ----
    if (w < 4) {
        const int rr = w >> 1;
        const int bb = blockIdx.x + rr * NBLK;
        const float* srcv = (w & 1) ? audio : video;
        float4 x = reinterpret_cast<const float4*>(srcv)[bb * 32 + lane];
        float ss = warp_sum(dot4(x, x));
        float inv = 1.0f / fmaxf(sqrtf(ss), 1e-12f);
        float4 nv = make_float4(x.x * inv, x.y * inv, x.z * inv, x.w * inv);
        if (w & 1) sa[rr][lane] = nv; else sv[rr][lane] = nv;
    }

    // ---- per-rep counting sort: 1024 keys, 256 buckets (row >> 11) ----
    for (int rep = 0; rep < 2; ++rep) {
        const int b = blockIdx.x + rep * NBLK;
        if (tid < NBKT) counts[tid] = 0;
        __syncthreads();
#pragma unroll
        for (int i = tid; i < NUM_NEG; i += 256) {
            const uint32_t row = (uint32_t)__ldg(neg_idx + (size_t)b * NUM_NEG + i);
            atomicAdd(&counts[row >> 11], 1);
        }
        __syncthreads();
        // warp 0: segmented exclusive scan of 256 counts (8 per lane)
        if (w == 0) {
            int seg[8];
            int segsum = 0;
#pragma unroll
            for (int k = 0; k < 8; ++k) { seg[k] = counts[lane * 8 + k]; segsum += seg[k]; }
            // inclusive warp scan of segsum -> exclusive base
            int inc = segsum;
#pragma unroll
            for (int o = 1; o < 32; o <<= 1) {
                int t = __shfl_up_sync(FULL, inc, o);
                if (lane >= o) inc += t;
            }
            int excl = inc - segsum;
#pragma unroll
            for (int k = 0; k < 8; ++k) { ocur[lane * 8 + k] = excl; excl += seg[k]; }
        }
        __syncthreads();
#pragma unroll
        for (int i = tid; i < NUM_NEG; i += 256) {
            const uint32_t row = (uint32_t)__ldg(neg_idx + (size_t)b * NUM_NEG + i);
            const int p = atomicAdd(&ocur[row >> 11], 1);
            sorted[rep][p] = (row << 10) | (uint32_t)i;
        }
        __syncthreads();
    }

    // this warp's rep: v/a slices in registers
    const float4 v0 = sv[wrep][c], v1 = sv[wrep][c + 8], v2 = sv[wrep][c + 16], v3 = sv[wrep][c + 24];
    const float4 a0 = sa[wrep][c], a1 = sa[wrep][c + 8], a2 = sa[wrep][c + 16], a3 = sa[wrep][c + 24];
    const uint32_t* skeys = sorted[wrep];

#define ISSUE(gexp)                                                           \
    do {                                                                      \
        const int g_loc = (gexp);                                             \
        _Pragma("unroll")                                                     \
        for (int i = 0; i < 4; ++i) {                                         \
            const int p = g_loc * 8 + wq * 2 + (i >> 1);                      \
            const int ni = (int)(skeys[p] >> 10);                             \
            const float4* src = ((i & 1) ? m2 : m1) + (size_t)ni * 32 + lane; \
            uint32_t dst = (uint32_t)__cvta_generic_to_shared(                \
                wring + ((g_loc & (D_ST - 1)) * 2048) + i * 512 + lane * 16); \
            cp_async16(dst, src);                                             \
        }                                                                     \
    } while (0)

#define COMPUTE(sexp)                                                         \
    do {                                                                      \
        const int s_loc = (sexp);                                             \
        const float4* buf = reinterpret_cast<const float4*>(                  \
            wring + (s_loc & (D_ST - 1)) * 2048) + (size_t)r * 32;            \
        const float4 x0 = buf[c], x1 = buf[c + 8], x2 = buf[c + 16], x3 = buf[c + 24]; \
        float dv = dot4(x0, v0) + dot4(x1, v1) + dot4(x2, v2) + dot4(x3, v3); \
        float da = dot4(x0, a0) + dot4(x1, a1) + dot4(x2, a2) + dot4(x3, a3); \
        grp8_sum2(dv, da);                                                    \
        if (c == 0) {                                                         \
            const int j = (int)(skeys[s_loc * 8 + wq * 2 + (r >> 1)] & 1023u);\
            if ((r & 1) == 0) {                                               \
                sout[wrep][1][j] = da * INV_TEMP;                             \
                sout[wrep][2][j] = dv * INV_TEMP;                             \
            } else {                                                          \
                sout[wrep][0][j] = dv * INV_TEMP;                             \
                sout[wrep][3][j] = da * INV_TEMP;                             \
            }                                                                 \
        }                                                                     \
    } while (0)

    // ---- prologue: issue stages 0..D_ST-2 ----
#pragma unroll
    for (int g = 0; g < D_ST - 1; ++g) { ISSUE(g); cp_commit(); }

    // ---- pos + self dots for this warp's rep (direct LDG, overlaps fill) ----
    {
        const int bp = blockIdx.x + wrep * NBLK;
#pragma unroll
        for (int t = 0; t < 2; ++t) {
            const int j  = wq * 8 + r * 2 + t;
            const int pi = __ldg(pos_idx + (size_t)bp * POS_K + j);
            const float4* p1 = m1 + (size_t)pi * 32 + c;
            const float4* p2 = m2 + (size_t)pi * 32 + c;
            float dvv = dot4(p1[0], v0) + dot4(p1[8], v1) + dot4(p1[16], v2) + dot4(p1[24], v3);
            float daa = dot4(p2[0], a0) + dot4(p2[8], a1) + dot4(p2[16], a2) + dot4(p2[24], a3);
            grp8_sum2(dvv, daa);
            if (c == 0) {
                out[O4 + (size_t)bp * POS_K + j] = dvv * INV_TEMP;
                out[O6 + (size_t)bp * POS_K + j] = daa * INV_TEMP;
            }
        }
        if (wq == 0 && r < 2) {   // warps 0 and 4: self dots for their rep
            const int yi = __ldg(y + bp);
            const float4* p = (r == 0 ? m1 : m2) + (size_t)yi * 32 + c;
            float d;
            if (r == 0) d = dot4(p[0], a0) + dot4(p[8], a1) + dot4(p[16], a2) + dot4(p[24], a3);
            else        d = dot4(p[0], v0) + dot4(p[8], v1) + dot4(p[16], v2) + dot4(p[24], v3);
#pragma unroll
            for (int o = 4; o; o >>= 1) d += __shfl_xor_sync(0x0000ffffu, d, o);
            if (c == 0) {
                if (r == 0) out[O2 + bp] = d * INV_TEMP;  // inst_a2v_pos
                else        out[O0 + bp] = d * INV_TEMP;  // inst_v2a_pos
            }
        }
    }

    // ---- steady state: branchless, unrolled; issue always valid ----
#pragma unroll 4
    for (int s = 0; s < NST - (D_ST - 1); ++s) {
        cp_wait<D_ST - 2>();                    // stage s complete
        __syncwarp();
        ISSUE(s + D_ST - 1);
        cp_commit();
        COMPUTE(s);
    }

    // ---- tail: all remaining groups drained once, then pure compute ----
    cp_wait<0>();
    __syncwarp();
#pragma unroll
    for (int s = NST - (D_ST - 1); s < NST; ++s) COMPUTE(s);

#undef ISSUE
#undef COMPUTE

    // ---- coalesced output flush ----
    __syncthreads();
    for (int rep = 0; rep < 2; ++rep) {
        const int b = blockIdx.x + rep * NBLK;
        for (int i = tid; i < NUM_NEG; i += 256) {
            const size_t o = (size_t)b * NUM_NEG + i;
            out[O1 + o] = sout[rep][0][i];
            out[O3 + o] = sout[rep][1][i];
            out[O5 + o] = sout[rep][2][i];
            out[O7 + o] = sout[rep][3][i];
        }
    }
}

extern "C" void kernel_launch(void* const* d_in, const int* in_sizes, int n_in,
                              void* d_out, int out_size)
{
    const float* video = (const float*)d_in[0];
    const float* audio = (const float*)d_in[1];
    const float4* m1   = (const float4*)d_in[2];
    const float4* m2   = (const float4*)d_in[3];
    const int* y       = (const int*)d_in[4];
    const int* pos_idx = (const int*)d_in[5];
    const int* neg_idx = (const int*)d_in[6];
    float* out         = (float*)d_out;

    const int dyn_smem = 8 * D_ST * 2048;   // 64 KB
    cudaFuncSetAttribute(avid_cma_kernel,
                         cudaFuncAttributeMaxDynamicSharedMemorySize, dyn_smem);

    avid_cma_kernel<<<NBLK, 256, dyn_smem>>>(video, audio, m1, m2, y,
                                             pos_idx, neg_idx, out);
}

// round 16
// speedup vs baseline: 1.5879x; 1.0005x over previous
#include <cuda_runtime.h>
#include <cstdint>

#define BS      512
#define DIM     128
#define POS_K   32
#define NUM_NEG 1024
#define INV_TEMP (1.0f / 0.07f)

#define NBLK    256                   // one resident wave (2/SM)
#define D_ST    4                     // per-warp ring depth
#define NST     128                   // stages per warp (1024 refs/rep / 8 per stage)
#define NBKT    256                   // sort buckets (row >> 11)

// Output layout (flattened tuple, float32):
#define O0 0          // inst_v2a_pos [512,1]
#define O1 512        // inst_v2a_neg [512,1024]
#define O2 524800     // inst_a2v_pos [512,1]
#define O3 525312     // inst_a2v_neg [512,1024]
#define O4 1049600    // pos_v2v_pos  [512,32]
#define O5 1065984    // pos_v2v_neg  [512,1024]
#define O6 1590272    // pos_a2a_pos  [512,32]
#define O7 1606656    // pos_a2a_neg  [512,1024]

#define FULL 0xffffffffu

// group barrier: 128 threads of rep-group `rep` (barrier ids 1,2)
#define GBAR(rep) asm volatile("bar.sync %0, 128;" :: "r"((rep) + 1) : "memory")

__device__ __forceinline__ float warp_sum(float x) {
#pragma unroll
    for (int o = 16; o; o >>= 1) x += __shfl_xor_sync(FULL, x, o);
    return x;
}

__device__ __forceinline__ float dot4(float4 x, float4 y) {
    return x.x * y.x + x.y * y.y + x.z * y.z + x.w * y.w;
}

__device__ __forceinline__ void grp8_sum2(float& a, float& b) {
#pragma unroll
    for (int o = 4; o; o >>= 1) {
        a += __shfl_xor_sync(FULL, a, o);
        b += __shfl_xor_sync(FULL, b, o);
    }
}

__device__ __forceinline__ void cp_async16(uint32_t dst_smem, const void* src) {
    asm volatile("cp.async.cg.shared.global [%0], [%1], 16;\n"
                 :: "r"(dst_smem), "l"(src) : "memory");
}
__device__ __forceinline__ void cp_commit() {
    asm volatile("cp.async.commit_group;\n" ::: "memory");
}
template <int N>
__device__ __forceinline__ void cp_wait() {
    asm volatile("cp.async.wait_group %0;\n" :: "n"(N) : "memory");
}

__global__ __launch_bounds__(256, 2)
void avid_cma_kernel(const float* __restrict__ video,
                     const float* __restrict__ audio,
                     const float4* __restrict__ m1,
                     const float4* __restrict__ m2,
                     const int* __restrict__ y,
                     const int* __restrict__ pos_idx,
                     const int* __restrict__ neg_idx,
                     float* __restrict__ out)
{
    extern __shared__ char ring[];              // 8 warps * D_ST * 2048 = 64 KB
    __shared__ uint32_t sorted[2][NUM_NEG];     // 8 KB per-rep sorted keys
    __shared__ int      counts[2][NBKT];        // 2 KB (per-group)
    __shared__ int      ocur[2][NBKT];          // 2 KB
    __shared__ float4   sv[2][32];
    __shared__ float4   sa[2][32];
    __shared__ float    sout[2][4][NUM_NEG];    // 32 KB output staging

    const int tid   = threadIdx.x;
    const int lane  = tid & 31;
    const int w     = tid >> 5;                 // 8 warps
    const int c     = lane & 7;
    const int r     = lane >> 3;
    const int wrep  = w >> 2;                   // group (rep) 0 or 1
    const int wq    = w & 3;                    // warp slot within group
    const int gtid  = tid & 127;                // thread id within group
    const int bp    = blockIdx.x + wrep * NBLK; // this group's batch row
    char* const wring = ring + (size_t)w * (D_ST * 2048);

    // ---- group-local init: normalize own v/a, zero own counts ----
    if (wq == 0) {
        float4 x = reinterpret_cast<const float4*>(video)[bp * 32 + lane];
        float ss = warp_sum(dot4(x, x));
        float inv = 1.0f / fmaxf(sqrtf(ss), 1e-12f);
        sv[wrep][lane] = make_float4(x.x * inv, x.y * inv, x.z * inv, x.w * inv);
    } else if (wq == 1) {
        float4 x = reinterpret_cast<const float4*>(audio)[bp * 32 + lane];
        float ss = warp_sum(dot4(x, x));
        float inv = 1.0f / fmaxf(sqrtf(ss), 1e-12f);
        sa[wrep][lane] = make_float4(x.x * inv, x.y * inv, x.z * inv, x.w * inv);
    }
    if (gtid < NBKT / 2) {                      // 128 threads zero 256 ints: 2 each
        counts[wrep][gtid] = 0;
        counts[wrep][gtid + 128] = 0;
    }
    GBAR(wrep);

    // ---- group-local counting sort: 1024 keys, 256 buckets (row >> 11) ----
#pragma unroll
    for (int i = gtid; i < NUM_NEG; i += 128) {
        const uint32_t row = (uint32_t)__ldg(neg_idx + (size_t)bp * NUM_NEG + i);
        atomicAdd(&counts[wrep][row >> 11], 1);
    }
    GBAR(wrep);
    if (wq == 0) {                              // group's warp 0: scan 256 counts
        int seg[8];
        int segsum = 0;
#pragma unroll
        for (int k = 0; k < 8; ++k) { seg[k] = counts[wrep][lane * 8 + k]; segsum += seg[k]; }
        int inc = segsum;
#pragma unroll
        for (int o = 1; o < 32; o <<= 1) {
            int t = __shfl_up_sync(FULL, inc, o);
            if (lane >= o) inc += t;
        }
        int excl = inc - segsum;
#pragma unroll
        for (int k = 0; k < 8; ++k) { ocur[wrep][lane * 8 + k] = excl; excl += seg[k]; }
    }
    GBAR(wrep);
#pragma unroll
    for (int i = gtid; i < NUM_NEG; i += 128) {
        const uint32_t row = (uint32_t)__ldg(neg_idx + (size_t)bp * NUM_NEG + i);
        const int p = atomicAdd(&ocur[wrep][row >> 11], 1);
        sorted[wrep][p] = (row << 10) | (uint32_t)i;
    }
    GBAR(wrep);                                 // sorted + sv/sa ready for group

    // this warp's rep: v/a slices in registers
    const float4 v0 = sv[wrep][c], v1 = sv[wrep][c + 8], v2 = sv[wrep][c + 16], v3 = sv[wrep][c + 24];
    const float4 a0 = sa[wrep][c], a1 = sa[wrep][c + 8], a2 = sa[wrep][c + 16], a3 = sa[wrep][c + 24];
    const uint32_t* skeys = sorted[wrep];

#define ISSUE(gexp)                                                           \
    do {                                                                      \
        const int g_loc = (gexp);                                             \
        _Pragma("unroll")                                                     \
        for (int i = 0; i < 4; ++i) {                                         \
            const int p = g_loc * 8 + wq * 2 + (i >> 1);                      \
            const int ni = (int)(skeys[p] >> 10);                             \
            const float4* src = ((i & 1) ? m2 : m1) + (size_t)ni * 32 + lane; \
            uint32_t dst = (uint32_t)__cvta_generic_to_shared(                \
                wring + ((g_loc & (D_ST - 1)) * 2048) + i * 512 + lane * 16); \
            cp_async16(dst, src);                                             \
        }                                                                     \
    } while (0)

#define COMPUTE(sexp)                                                         \
    do {                                                                      \
        const int s_loc = (sexp);                                             \
        const float4* buf = reinterpret_cast<const float4*>(                  \
            wring + (s_loc & (D_ST - 1)) * 2048) + (size_t)r * 32;            \
        const float4 x0 = buf[c], x1 = buf[c + 8], x2 = buf[c + 16], x3 = buf[c + 24]; \
        float dv = dot4(x0, v0) + dot4(x1, v1) + dot4(x2, v2) + dot4(x3, v3); \
        float da = dot4(x0, a0) + dot4(x1, a1) + dot4(x2, a2) + dot4(x3, a3); \
        grp8_sum2(dv, da);                                                    \
        if (c == 0) {                                                         \
            const int j = (int)(skeys[s_loc * 8 + wq * 2 + (r >> 1)] & 1023u);\
            if ((r & 1) == 0) {                                               \
                sout[wrep][1][j] = da * INV_TEMP;                             \
                sout[wrep][2][j] = dv * INV_TEMP;                             \
            } else {                                                          \
                sout[wrep][0][j] = dv * INV_TEMP;                             \
                sout[wrep][3][j] = da * INV_TEMP;                             \
            }                                                                 \
        }                                                                     \
    } while (0)

    // ---- prologue: issue stages 0..D_ST-2 ----
#pragma unroll
    for (int g = 0; g < D_ST - 1; ++g) { ISSUE(g); cp_commit(); }

    // ---- pos + self dots for this group's rep (direct LDG, overlaps fill) ----
    {
#pragma unroll
        for (int t = 0; t < 2; ++t) {
            const int j  = wq * 8 + r * 2 + t;
            const int pi = __ldg(pos_idx + (size_t)bp * POS_K + j);
            const float4* p1 = m1 + (size_t)pi * 32 + c;
            const float4* p2 = m2 + (size_t)pi * 32 + c;
            float dvv = dot4(p1[0], v0) + dot4(p1[8], v1) + dot4(p1[16], v2) + dot4(p1[24], v3);
            float daa = dot4(p2[0], a0) + dot4(p2[8], a1) + dot4(p2[16], a2) + dot4(p2[24], a3);
            grp8_sum2(dvv, daa);
            if (c == 0) {
                out[O4 + (size_t)bp * POS_K + j] = dvv * INV_TEMP;
                out[O6 + (size_t)bp * POS_K + j] = daa * INV_TEMP;
            }
        }
        if (wq == 0 && r < 2) {                 // group's warp 0: self dots
            const int yi = __ldg(y + bp);
            const float4* p = (r == 0 ? m1 : m2) + (size_t)yi * 32 + c;
            float d;
            if (r == 0) d = dot4(p[0], a0) + dot4(p[8], a1) + dot4(p[16], a2) + dot4(p[24], a3);
            else        d = dot4(p[0], v0) + dot4(p[8], v1) + dot4(p[16], v2) + dot4(p[24], v3);
#pragma unroll
            for (int o = 4; o; o >>= 1) d += __shfl_xor_sync(0x0000ffffu, d, o);
            if (c == 0) {
                if (r == 0) out[O2 + bp] = d * INV_TEMP;  // inst_a2v_pos
                else        out[O0 + bp] = d * INV_TEMP;  // inst_v2a_pos
            }
        }
    }

    // ---- steady state: branchless, unrolled ----
#pragma unroll 4
    for (int s = 0; s < NST - (D_ST - 1); ++s) {
        cp_wait<D_ST - 2>();                    // stage s complete
        __syncwarp();
        ISSUE(s + D_ST - 1);
        cp_commit();
        COMPUTE(s);
    }

    // ---- tail: drain once, pure compute ----
    cp_wait<0>();
    __syncwarp();
#pragma unroll
    for (int s = NST - (D_ST - 1); s < NST; ++s) COMPUTE(s);

#undef ISSUE
#undef COMPUTE

    // ---- group-local coalesced flush (overlaps the other group's sweep) ----
    GBAR(wrep);                                 // all 4 warps of group done
#pragma unroll
    for (int i = gtid; i < NUM_NEG; i += 128) {
        const size_t o = (size_t)bp * NUM_NEG + i;
        out[O1 + o] = sout[wrep][0][i];
        out[O3 + o] = sout[wrep][1][i];
        out[O5 + o] = sout[wrep][2][i];
        out[O7 + o] = sout[wrep][3][i];
    }
}

extern "C" void kernel_launch(void* const* d_in, const int* in_sizes, int n_in,
                              void* d_out, int out_size)
{
    const float* video = (const float*)d_in[0];
    const float* audio = (const float*)d_in[1];
    const float4* m1   = (const float4*)d_in[2];
    const float4* m2   = (const float4*)d_in[3];
    const int* y       = (const int*)d_in[4];
    const int* pos_idx = (const int*)d_in[5];
    const int* neg_idx = (const int*)d_in[6];
    float* out         = (float*)d_out;

    const int dyn_smem = 8 * D_ST * 2048;   // 64 KB
    cudaFuncSetAttribute(avid_cma_kernel,
                         cudaFuncAttributeMaxDynamicSharedMemorySize, dyn_smem);

    avid_cma_kernel<<<NBLK, 256, dyn_smem>>>(video, audio, m1, m2, y,
                                             pos_idx, neg_idx, out);
}

// round 17
// speedup vs baseline: 1.5981x; 1.0064x over previous
#include <cuda_runtime.h>
#include <cstdint>

#define BS      512
#define DIM     128
#define POS_K   32
#define NUM_NEG 1024
#define INV_TEMP (1.0f / 0.07f)

#define NBLK    256                   // one resident wave (2/SM)
#define D_ST    4                     // per-warp ring depth
#define NST     128                   // stages per warp (1024 refs/rep / 8 per stage)
#define NBKT    256                   // sort buckets (row >> 11)

// Output layout (flattened tuple, float32):
#define O0 0          // inst_v2a_pos [512,1]
#define O1 512        // inst_v2a_neg [512,1024]
#define O2 524800     // inst_a2v_pos [512,1]
#define O3 525312     // inst_a2v_neg [512,1024]
#define O4 1049600    // pos_v2v_pos  [512,32]
#define O5 1065984    // pos_v2v_neg  [512,1024]
#define O6 1590272    // pos_a2a_pos  [512,32]
#define O7 1606656    // pos_a2a_neg  [512,1024]

#define FULL 0xffffffffu

// group barrier: 128 threads of rep-group `rep` (barrier ids 1,2)
#define GBAR(rep) asm volatile("bar.sync %0, 128;" :: "r"((rep) + 1) : "memory")

__device__ __forceinline__ float warp_sum(float x) {
#pragma unroll
    for (int o = 16; o; o >>= 1) x += __shfl_xor_sync(FULL, x, o);
    return x;
}

__device__ __forceinline__ float dot4(float4 x, float4 y) {
    return x.x * y.x + x.y * y.y + x.z * y.z + x.w * y.w;
}

__device__ __forceinline__ void grp8_sum2(float& a, float& b) {
#pragma unroll
    for (int o = 4; o; o >>= 1) {
        a += __shfl_xor_sync(FULL, a, o);
        b += __shfl_xor_sync(FULL, b, o);
    }
}

__device__ __forceinline__ void cp_async16(uint32_t dst_smem, const void* src) {
    asm volatile("cp.async.cg.shared.global [%0], [%1], 16;\n"
                 :: "r"(dst_smem), "l"(src) : "memory");
}
__device__ __forceinline__ void cp_commit() {
    asm volatile("cp.async.commit_group;\n" ::: "memory");
}
template <int N>
__device__ __forceinline__ void cp_wait() {
    asm volatile("cp.async.wait_group %0;\n" :: "n"(N) : "memory");
}

__global__ __launch_bounds__(256, 2)
void avid_cma_kernel(const float* __restrict__ video,
                     const float* __restrict__ audio,
                     const float4* __restrict__ m1,
                     const float4* __restrict__ m2,
                     const int* __restrict__ y,
                     const int* __restrict__ pos_idx,
                     const int* __restrict__ neg_idx,
                     float* __restrict__ out)
{
    extern __shared__ char ring[];              // 8 warps * D_ST * 2048 = 64 KB
    __shared__ uint32_t sorted[2][NUM_NEG];     // 8 KB per-rep sorted keys
    __shared__ int      counts[2][NBKT];        // 2 KB (per-group)
    __shared__ int      ocur[2][NBKT];          // 2 KB
    __shared__ float4   sv[2][32];
    __shared__ float4   sa[2][32];
    __shared__ float    sout[2][4][NUM_NEG];    // 32 KB output staging

    const int tid   = threadIdx.x;
    const int lane  = tid & 31;
    const int w     = tid >> 5;                 // 8 warps
    const int c     = lane & 7;
    const int r     = lane >> 3;
    const int wrep  = w >> 2;                   // group (rep) 0 or 1
    const int wq    = w & 3;                    // warp slot within group
    const int gtid  = tid & 127;                // thread id within group
    const int bp    = blockIdx.x + wrep * NBLK; // this group's batch row
    char* const wring = ring + (size_t)w * (D_ST * 2048);

    // ---- group-local init: normalize own v/a, zero own counts ----
    if (wq == 0) {
        float4 x = reinterpret_cast<const float4*>(video)[bp * 32 + lane];
        float ss = warp_sum(dot4(x, x));
        float inv = 1.0f / fmaxf(sqrtf(ss), 1e-12f);
        sv[wrep][lane] = make_float4(x.x * inv, x.y * inv, x.z * inv, x.w * inv);
    } else if (wq == 1) {
        float4 x = reinterpret_cast<const float4*>(audio)[bp * 32 + lane];
        float ss = warp_sum(dot4(x, x));
        float inv = 1.0f / fmaxf(sqrtf(ss), 1e-12f);
        sa[wrep][lane] = make_float4(x.x * inv, x.y * inv, x.z * inv, x.w * inv);
    }
    if (gtid < NBKT / 2) {
        counts[wrep][gtid] = 0;
        counts[wrep][gtid + 128] = 0;
    }
    GBAR(wrep);

    // ---- group-local counting sort: 1024 keys, 256 buckets (row >> 11) ----
#pragma unroll
    for (int i = gtid; i < NUM_NEG; i += 128) {
        const uint32_t row = (uint32_t)__ldg(neg_idx + (size_t)bp * NUM_NEG + i);
        atomicAdd(&counts[wrep][row >> 11], 1);
    }
    GBAR(wrep);
    if (wq == 0) {                              // group's warp 0: scan 256 counts
        int seg[8];
        int segsum = 0;
#pragma unroll
        for (int k = 0; k < 8; ++k) { seg[k] = counts[wrep][lane * 8 + k]; segsum += seg[k]; }
        int inc = segsum;
#pragma unroll
        for (int o = 1; o < 32; o <<= 1) {
            int t = __shfl_up_sync(FULL, inc, o);
            if (lane >= o) inc += t;
        }
        int excl = inc - segsum;
#pragma unroll
        for (int k = 0; k < 8; ++k) { ocur[wrep][lane * 8 + k] = excl; excl += seg[k]; }
    }
    GBAR(wrep);
#pragma unroll
    for (int i = gtid; i < NUM_NEG; i += 128) {
        const uint32_t row = (uint32_t)__ldg(neg_idx + (size_t)bp * NUM_NEG + i);
        const int p = atomicAdd(&ocur[wrep][row >> 11], 1);
        sorted[wrep][p] = (row << 10) | (uint32_t)i;
    }
    GBAR(wrep);                                 // sorted + sv/sa ready for group

    // this warp's rep: v/a slices in registers
    const float4 v0 = sv[wrep][c], v1 = sv[wrep][c + 8], v2 = sv[wrep][c + 16], v3 = sv[wrep][c + 24];
    const float4 a0 = sa[wrep][c], a1 = sa[wrep][c + 8], a2 = sa[wrep][c + 16], a3 = sa[wrep][c + 24];
    const uint32_t* skeys = sorted[wrep];

#define ISSUE(gexp)                                                           \
    do {                                                                      \
        const int g_loc = (gexp);                                             \
        _Pragma("unroll")                                                     \
        for (int i = 0; i < 4; ++i) {                                         \
            const int p = g_loc * 8 + wq * 2 + (i >> 1);                      \
            const int ni = (int)(skeys[p] >> 10);                             \
            const float4* src = ((i & 1) ? m2 : m1) + (size_t)ni * 32 + lane; \
            uint32_t dst = (uint32_t)__cvta_generic_to_shared(                \
                wring + ((g_loc & (D_ST - 1)) * 2048) + i * 512 + lane * 16); \
            cp_async16(dst, src);                                             \
        }                                                                     \
    } while (0)

    // COMPUTE with key prefetched (jkey read before the wait, passed in)
#define COMPUTE(sexp, jkey)                                                   \
    do {                                                                      \
        const int s_loc = (sexp);                                             \
        const float4* buf = reinterpret_cast<const float4*>(                  \
            wring + (s_loc & (D_ST - 1)) * 2048) + (size_t)r * 32;            \
        const float4 x0 = buf[c], x1 = buf[c + 8], x2 = buf[c + 16], x3 = buf[c + 24]; \
        float dv = dot4(x0, v0) + dot4(x1, v1) + dot4(x2, v2) + dot4(x3, v3); \
        float da = dot4(x0, a0) + dot4(x1, a1) + dot4(x2, a2) + dot4(x3, a3); \
        grp8_sum2(dv, da);                                                    \
        if (c == 0) {                                                         \
            const int j = (int)((jkey) & 1023u);                              \
            if ((r & 1) == 0) {                                               \
                sout[wrep][1][j] = da * INV_TEMP;                             \
                sout[wrep][2][j] = dv * INV_TEMP;                             \
            } else {                                                          \
                sout[wrep][0][j] = dv * INV_TEMP;                             \
                sout[wrep][3][j] = da * INV_TEMP;                             \
            }                                                                 \
        }                                                                     \
    } while (0)

    // ---- prologue: issue stages 0..D_ST-2 ----
#pragma unroll
    for (int g = 0; g < D_ST - 1; ++g) { ISSUE(g); cp_commit(); }

    // ---- pos + self dots for this group's rep (direct LDG, overlaps fill) ----
    {
#pragma unroll
        for (int t = 0; t < 2; ++t) {
            const int j  = wq * 8 + r * 2 + t;
            const int pi = __ldg(pos_idx + (size_t)bp * POS_K + j);
            const float4* p1 = m1 + (size_t)pi * 32 + c;
            const float4* p2 = m2 + (size_t)pi * 32 + c;
            float dvv = dot4(p1[0], v0) + dot4(p1[8], v1) + dot4(p1[16], v2) + dot4(p1[24], v3);
            float daa = dot4(p2[0], a0) + dot4(p2[8], a1) + dot4(p2[16], a2) + dot4(p2[24], a3);
            grp8_sum2(dvv, daa);
            if (c == 0) {
                out[O4 + (size_t)bp * POS_K + j] = dvv * INV_TEMP;
                out[O6 + (size_t)bp * POS_K + j] = daa * INV_TEMP;
            }
        }
        if (wq == 0 && r < 2) {                 // group's warp 0: self dots
            const int yi = __ldg(y + bp);
            const float4* p = (r == 0 ? m1 : m2) + (size_t)yi * 32 + c;
            float d;
            if (r == 0) d = dot4(p[0], a0) + dot4(p[8], a1) + dot4(p[16], a2) + dot4(p[24], a3);
            else        d = dot4(p[0], v0) + dot4(p[8], v1) + dot4(p[16], v2) + dot4(p[24], v3);
#pragma unroll
            for (int o = 4; o; o >>= 1) d += __shfl_xor_sync(0x0000ffffu, d, o);
            if (c == 0) {
                if (r == 0) out[O2 + bp] = d * INV_TEMP;  // inst_a2v_pos
                else        out[O0 + bp] = d * INV_TEMP;  // inst_v2a_pos
            }
        }
    }

    // ---- steady state: ISSUE BEFORE WAIT (load issue decoupled from
    //      completion; slot (s+3)%4 was freed by compute(s-1)) ----
#pragma unroll 4
    for (int s = 0; s < NST - (D_ST - 1); ++s) {
        const uint32_t jkey = skeys[s * 8 + wq * 2 + (r >> 1)];  // prefetch key
        ISSUE(s + D_ST - 1);
        cp_commit();                            // pending: s..s+3 (4 groups)
        cp_wait<D_ST - 1>();                    // gate on stage s only
        __syncwarp();
        COMPUTE(s, jkey);
    }

    // ---- tail: drain once, pure compute ----
    cp_wait<0>();
    __syncwarp();
#pragma unroll
    for (int s = NST - (D_ST - 1); s < NST; ++s) {
        const uint32_t jkey = skeys[s * 8 + wq * 2 + (r >> 1)];
        COMPUTE(s, jkey);
    }

#undef ISSUE
#undef COMPUTE

    // ---- group-local coalesced flush (overlaps the other group's sweep) ----
    GBAR(wrep);                                 // all 4 warps of group done
#pragma unroll
    for (int i = gtid; i < NUM_NEG; i += 128) {
        const size_t o = (size_t)bp * NUM_NEG + i;
        out[O1 + o] = sout[wrep][0][i];
        out[O3 + o] = sout[wrep][1][i];
        out[O5 + o] = sout[wrep][2][i];
        out[O7 + o] = sout[wrep][3][i];
    }
}

extern "C" void kernel_launch(void* const* d_in, const int* in_sizes, int n_in,
                              void* d_out, int out_size)
{
    const float* video = (const float*)d_in[0];
    const float* audio = (const float*)d_in[1];
    const float4* m1   = (const float4*)d_in[2];
    const float4* m2   = (const float4*)d_in[3];
    const int* y       = (const int*)d_in[4];
    const int* pos_idx = (const int*)d_in[5];
    const int* neg_idx = (const int*)d_in[6];
    float* out         = (float*)d_out;

    const int dyn_smem = 8 * D_ST * 2048;   // 64 KB
    cudaFuncSetAttribute(avid_cma_kernel,
                         cudaFuncAttributeMaxDynamicSharedMemorySize, dyn_smem);

    avid_cma_kernel<<<NBLK, 256, dyn_smem>>>(video, audio, m1, m2, y,
                                             pos_idx, neg_idx, out);
}